// round 5
// baseline (speedup 1.0000x reference)
#include <cuda_runtime.h>
#include <float.h>

#define N_Q   4096
#define M_P   32768
#define W_F   768
#define K_NN  4
#define R2    0.25f

#define BM 128
#define BN 64
#define BK 16

// Scratch (no allocation allowed): kNN indices (-1 = masked) and raw agg GEMM result.
__device__ int   g_idx[N_Q * K_NN];
__device__ float g_aggraw[N_Q * W_F];

__device__ __forceinline__ bool pair_less(float d1, int i1, float d2, int i2) {
    return (d1 < d2) || (d1 == d2 && i1 < i2);
}

// ---------------------------------------------------------------------------
// Kernel 1: top-4 nearest neighbors per query.
// This round: qq/pp via DESCENDING FMA:  qq = fma(x,x, fma(y,y, rn(z*z)))
// dot stays ASCENDING FMA (validated: both F~2 rounds used it):
//   dot = fma(qz,pz, fma(qy,py, rn(qx*px)))
// combine: d2 = rn(rn(qq+pp) - 2*dot)   (bit-equivalent to all groupings)
// ---------------------------------------------------------------------------
__global__ __launch_bounds__(256) void topk_kernel(const float* __restrict__ q_pos,
                                                   const float* __restrict__ pts) {
    const int n   = blockIdx.x;
    const int tid = threadIdx.x;

    const float qx = q_pos[n * 3 + 0];
    const float qy = q_pos[n * 3 + 1];
    const float qz = q_pos[n * 3 + 2];
    const float qq = __fmaf_rn(qx, qx, __fmaf_rn(qy, qy, __fmul_rn(qz, qz)));

    float bd[4] = {FLT_MAX, FLT_MAX, FLT_MAX, FLT_MAX};
    int   bi[4] = {-1, -1, -1, -1};

    for (int j = tid; j < M_P; j += 256) {
        const float px = pts[j * 3 + 0];
        const float py = pts[j * 3 + 1];
        const float pz = pts[j * 3 + 2];
        const float pp = __fmaf_rn(px, px, __fmaf_rn(py, py, __fmul_rn(pz, pz)));
        // ASCENDING fma dot chain.
        float dot = __fmul_rn(qx, px);
        dot = __fmaf_rn(qy, py, dot);
        dot = __fmaf_rn(qz, pz, dot);
        const float t1 = __fadd_rn(qq, pp);
        const float d2 = __fadd_rn(t1, -__fmul_rn(2.0f, dot));
        if (pair_less(d2, j, bd[3], bi[3])) {
            bd[3] = d2; bi[3] = j;
            #pragma unroll
            for (int p = 3; p > 0; --p) {
                if (pair_less(bd[p], bi[p], bd[p - 1], bi[p - 1])) {
                    float td = bd[p]; bd[p] = bd[p - 1]; bd[p - 1] = td;
                    int   ti = bi[p]; bi[p] = bi[p - 1]; bi[p - 1] = ti;
                }
            }
        }
    }

    __shared__ float sd[256 * 4];
    __shared__ int   si[256 * 4];
    #pragma unroll
    for (int k = 0; k < 4; k++) { sd[tid * 4 + k] = bd[k]; si[tid * 4 + k] = bi[k]; }
    __syncthreads();

    // Tree merge of sorted 4-lists.
    for (int s = 128; s > 0; s >>= 1) {
        if (tid < s) {
            float ad[4], xd[4]; int ai[4], xi[4];
            #pragma unroll
            for (int k = 0; k < 4; k++) {
                ad[k] = sd[tid * 4 + k];        ai[k] = si[tid * 4 + k];
                xd[k] = sd[(tid + s) * 4 + k];  xi[k] = si[(tid + s) * 4 + k];
            }
            float rd[4]; int ri[4];
            int ia = 0, ib = 0;
            #pragma unroll
            for (int t = 0; t < 4; t++) {
                bool takeA = pair_less(ad[ia], ai[ia], xd[ib], xi[ib]);
                rd[t] = takeA ? ad[ia] : xd[ib];
                ri[t] = takeA ? ai[ia] : xi[ib];
                if (takeA) ia++; else ib++;
            }
            #pragma unroll
            for (int k = 0; k < 4; k++) { sd[tid * 4 + k] = rd[k]; si[tid * 4 + k] = ri[k]; }
        }
        __syncthreads();
    }

    if (tid == 0) {
        #pragma unroll
        for (int k = 0; k < 4; k++)
            g_idx[n * 4 + k] = (sd[k] <= R2) ? si[k] : -1;   // radius mask
    }
}

// ---------------------------------------------------------------------------
// Kernel 2: gathered SGEMM  C[4096,768] = A[4096,3072] * W_agg[3072,768] + b_agg
// where A[n, k*768+w] = (idx>=0) ? feats[idx[n,k], w] : 0. Gather fused into
// the A-tile load; per-block idx table cached in smem.
// ---------------------------------------------------------------------------
__global__ __launch_bounds__(256) void gemm_kernel(const float* __restrict__ feats,
                                                   const float* __restrict__ Wagg,
                                                   const float* __restrict__ bagg) {
    __shared__ float As[BK][BM];       // 8 KB, transposed for broadcast reads
    __shared__ float Bs[BK][BN];       // 4 KB
    __shared__ int   sidx[BM][4];      // 2 KB

    const int tid = threadIdx.x;
    const int bm  = blockIdx.y * BM;
    const int bn  = blockIdx.x * BN;

    for (int t = tid; t < BM * 4; t += 256)
        sidx[t >> 2][t & 3] = g_idx[(bm + (t >> 2)) * 4 + (t & 3)];
    __syncthreads();

    float acc[8][4];
    #pragma unroll
    for (int r = 0; r < 8; r++)
        #pragma unroll
        for (int c = 0; c < 4; c++) acc[r][c] = 0.0f;

    const int rg = tid >> 4;   // 0..15 -> 8 rows each
    const int cg = tid & 15;   // 0..15 -> 4 cols each

    for (int kt = 0; kt < K_NN * W_F; kt += BK) {
        const int kidx  = kt / W_F;            // constant within tile (768 % 16 == 0)
        const int wbase = kt - kidx * W_F;

        // Load A tile (gathered): 2048 floats, 2 x float4 per thread.
        #pragma unroll
        for (int v = 0; v < 2; v++) {
            const int s2  = tid + v * 256;
            const int row = s2 >> 2;
            const int kk  = (s2 & 3) << 2;
            const int prow = sidx[row][kidx];
            float4 a = make_float4(0.f, 0.f, 0.f, 0.f);
            if (prow >= 0)
                a = *reinterpret_cast<const float4*>(&feats[prow * W_F + wbase + kk]);
            As[kk + 0][row] = a.x;
            As[kk + 1][row] = a.y;
            As[kk + 2][row] = a.z;
            As[kk + 3][row] = a.w;
        }
        // Load B tile: 1024 floats, 1 x float4 per thread.
        {
            const int kkb = tid >> 4;
            const int jb  = (tid & 15) << 2;
            float4 b = *reinterpret_cast<const float4*>(&Wagg[(kt + kkb) * W_F + bn + jb]);
            *reinterpret_cast<float4*>(&Bs[kkb][jb]) = b;
        }
        __syncthreads();

        #pragma unroll
        for (int kk = 0; kk < BK; kk++) {
            float4 a0 = *reinterpret_cast<const float4*>(&As[kk][rg * 8 + 0]);
            float4 a1 = *reinterpret_cast<const float4*>(&As[kk][rg * 8 + 4]);
            float4 bv = *reinterpret_cast<const float4*>(&Bs[kk][cg * 4]);
            const float ar[8] = {a0.x, a0.y, a0.z, a0.w, a1.x, a1.y, a1.z, a1.w};
            const float br[4] = {bv.x, bv.y, bv.z, bv.w};
            #pragma unroll
            for (int r = 0; r < 8; r++)
                #pragma unroll
                for (int c = 0; c < 4; c++)
                    acc[r][c] += ar[r] * br[c];
        }
        __syncthreads();
    }

    // Epilogue: + b_agg, store raw (LayerNorm done in kernel 3).
    #pragma unroll
    for (int r = 0; r < 8; r++) {
        const int grow = bm + rg * 8 + r;
        const int gcol = bn + cg * 4;
        float4 o;
        o.x = acc[r][0] + bagg[gcol + 0];
        o.y = acc[r][1] + bagg[gcol + 1];
        o.z = acc[r][2] + bagg[gcol + 2];
        o.w = acc[r][3] + bagg[gcol + 3];
        *reinterpret_cast<float4*>(&g_aggraw[grow * W_F + gcol]) = o;
    }
}

// ---------------------------------------------------------------------------
// Kernel 3: pos embedding GEMV (K=6) + two LayerNorms + add.
// ---------------------------------------------------------------------------
__device__ __forceinline__ float block_sum(float v, float* sbuf) {
    __syncthreads();  // protect sbuf reuse across calls
    #pragma unroll
    for (int o = 16; o > 0; o >>= 1) v += __shfl_xor_sync(0xffffffffu, v, o);
    const int wid = threadIdx.x >> 5, lane = threadIdx.x & 31;
    if (lane == 0) sbuf[wid] = v;
    __syncthreads();
    if (wid == 0) {
        float x = (lane < 8) ? sbuf[lane] : 0.0f;
        #pragma unroll
        for (int o = 4; o > 0; o >>= 1) x += __shfl_xor_sync(0xffffffffu, x, o);
        if (lane == 0) sbuf[0] = x;
    }
    __syncthreads();
    return sbuf[0];
}

__global__ __launch_bounds__(256) void ln_kernel(const float* __restrict__ pos_in,
                                                 const float* __restrict__ Wpos,
                                                 const float* __restrict__ bpos,
                                                 const float* __restrict__ gagg,
                                                 const float* __restrict__ beagg,
                                                 const float* __restrict__ gpos,
                                                 const float* __restrict__ bepos,
                                                 float* __restrict__ out) {
    const int n   = blockIdx.x;
    const int tid = threadIdx.x;
    __shared__ float pin[6];
    __shared__ float sred[32];
    if (tid < 6) pin[tid] = pos_in[n * 6 + tid];
    __syncthreads();

    float a[3], p[3];
    float sa = 0.f, sp = 0.f;
    #pragma unroll
    for (int t = 0; t < 3; t++) {
        const int j = tid + t * 256;
        a[t] = g_aggraw[n * W_F + j];
        float pv = bpos[j];
        #pragma unroll
        for (int i = 0; i < 6; i++) pv += pin[i] * Wpos[i * W_F + j];
        p[t] = pv;
        sa += a[t]; sp += p[t];
    }
    const float ma = block_sum(sa, sred) * (1.0f / 768.0f);
    const float mp = block_sum(sp, sred) * (1.0f / 768.0f);

    float va = 0.f, vp = 0.f;
    #pragma unroll
    for (int t = 0; t < 3; t++) {
        const float da = a[t] - ma; va += da * da;
        const float dp = p[t] - mp; vp += dp * dp;
    }
    va = block_sum(va, sred) * (1.0f / 768.0f);
    vp = block_sum(vp, sred) * (1.0f / 768.0f);
    const float inva = rsqrtf(va + 1e-12f);
    const float invp = rsqrtf(vp + 1e-12f);

    #pragma unroll
    for (int t = 0; t < 3; t++) {
        const int j = tid + t * 256;
        out[n * W_F + j] = (a[t] - ma) * inva * gagg[j] + beagg[j]
                         + (p[t] - mp) * invp * gpos[j] + bepos[j];
    }
}

// ---------------------------------------------------------------------------
extern "C" void kernel_launch(void* const* d_in, const int* in_sizes, int n_in,
                              void* d_out, int out_size) {
    const float* q_pos  = (const float*)d_in[0];
    const float* pts    = (const float*)d_in[1];
    const float* feats  = (const float*)d_in[2];
    const float* pos_in = (const float*)d_in[3];
    const float* Wagg   = (const float*)d_in[4];
    const float* bagg   = (const float*)d_in[5];
    const float* gagg   = (const float*)d_in[6];
    const float* beagg  = (const float*)d_in[7];
    const float* Wpos   = (const float*)d_in[8];
    const float* bpos   = (const float*)d_in[9];
    const float* gpos   = (const float*)d_in[10];
    const float* bepos  = (const float*)d_in[11];
    float* out = (float*)d_out;

    topk_kernel<<<N_Q, 256>>>(q_pos, pts);

    dim3 ggrid(W_F / BN, N_Q / BM);   // 12 x 32 = 384 blocks
    gemm_kernel<<<ggrid, 256>>>(feats, Wagg, bagg);

    ln_kernel<<<N_Q, 256>>>(pos_in, Wpos, bpos, gagg, beagg, gpos, bepos, out);
}